// round 17
// baseline (speedup 1.0000x reference)
#include <cuda_runtime.h>

#define NN 40960
#define PT (4*NN)

__device__ float g_f[(long)PT*32];   // f = relu(s2*(W2@feat)+b2), [point][32]
__device__ float g_z[(long)PT*32];   // z = s3 * (W3a @ f), [point][32]
__device__ int g_is64;

__device__ __forceinline__ unsigned long long pack2(float lo, float hi){
    unsigned long long r;
    asm("mov.b64 %0, {%1, %2};" : "=l"(r) : "f"(lo), "f"(hi));
    return r;
}
__device__ __forceinline__ void unpack2(unsigned long long v, float& lo, float& hi){
    asm("mov.b64 {%0, %1}, %2;" : "=f"(lo), "=f"(hi) : "l"(v));
}
__device__ __forceinline__ unsigned long long fma2(unsigned long long a, unsigned long long b, unsigned long long c){
    unsigned long long d;
    asm("fma.rn.f32x2 %0, %1, %2, %3;" : "=l"(d) : "l"(a), "l"(b), "l"(c));
    return d;
}

// ---------------------------------------------------------------------------
// Kernel A: per point  f = relu(s2*(W2@x)+b2);  z = s3*(W3a@f)
__global__ void __launch_bounds__(256) kernelA(
    const float* __restrict__ feat,
    const float* __restrict__ W2, const float* __restrict__ g2, const float* __restrict__ b2,
    const float* __restrict__ W3, const float* __restrict__ g3,
    const int* __restrict__ neigh32)
{
    __shared__ __align__(16) float tile[64*68];      // [n][d] pitch 68 (16B rows)
    __shared__ __align__(16) float hs[8][2][32];     // double-buffered f

    const int tid  = threadIdx.x;
    const int lane = tid & 31;
    const int wid  = tid >> 5;

    if (blockIdx.x == 0 && tid == 0){
        int allzero = 1;
        #pragma unroll 1
        for (int i = 0; i < 128; i++)
            if (neigh32[2*i + 1] != 0) { allzero = 0; break; }
        g_is64 = allzero;
    }

    const float inv = rsqrtf(1.0f + 1e-5f);
    const float s2 = g2[lane]*inv, bb2 = b2[lane];
    const float s3 = g3[lane]*inv;

    unsigned long long w2p[32], w3ap[16];
    for (int i = tid; i < 2048; i += 256) tile[(i>>6)*66 + (i&63)] = W2[i];
    __syncthreads();
    #pragma unroll
    for (int c = 0; c < 32; c++)
        w2p[c] = pack2(tile[lane*66 + 2*c]*s2, tile[lane*66 + 2*c + 1]*s2);
    __syncthreads();
    for (int i = tid; i < 2048; i += 256) tile[(i>>6)*66 + (i&63)] = W3[i];
    __syncthreads();
    #pragma unroll
    for (int c = 0; c < 16; c++)
        w3ap[c] = pack2(tile[lane*66 + 2*c]*s3, tile[lane*66 + 2*c + 1]*s3);

    #pragma unroll 1
    for (int blk = blockIdx.x; blk < 2560; blk += gridDim.x){
        const int b  = blk / 640;
        const int n0 = (blk - b*640) * 64;
        const float* fb = feat + (long)b*64*NN;
        __syncthreads();
        for (int i = tid; i < 4096; i += 256){
            int d = i >> 6, n = i & 63;
            tile[n*68 + d] = fb[(long)d*NN + n0 + n];
        }
        __syncthreads();

        #pragma unroll 1
        for (int j = 0; j < 8; j++){
            const int n = wid*8 + j;
            const ulonglong2* xp2 = (const ulonglong2*)(tile + n*68);
            unsigned long long a0=0ull, a1=0ull, a2=0ull, a3=0ull;
            #pragma unroll
            for (int c = 0; c < 16; c += 2){
                ulonglong2 v0 = xp2[c], v1 = xp2[c+1];
                a0 = fma2(w2p[2*c+0], v0.x, a0);
                a1 = fma2(w2p[2*c+1], v0.y, a1);
                a2 = fma2(w2p[2*c+2], v1.x, a2);
                a3 = fma2(w2p[2*c+3], v1.y, a3);
            }
            float l0,h0,l1,h1,l2,h2,l3,h3;
            unpack2(a0,l0,h0); unpack2(a1,l1,h1); unpack2(a2,l2,h2); unpack2(a3,l3,h3);
            float f = fmaxf((l0+h0)+(l1+h1)+(l2+h2)+(l3+h3) + bb2, 0.0f);

            const long p = (long)b*NN + n0 + n;
            float* hb = hs[wid][j & 1];
            hb[lane] = f;
            g_f[p*32 + lane] = f;
            __syncwarp();

            const ulonglong2* hp2 = (const ulonglong2*)hb;
            unsigned long long z0=0ull, z1=0ull, z2=0ull, z3=0ull;
            #pragma unroll
            for (int c = 0; c < 8; c += 2){
                ulonglong2 v0 = hp2[c], v1 = hp2[c+1];
                z0 = fma2(w3ap[2*c+0], v0.x, z0);
                z1 = fma2(w3ap[2*c+1], v0.y, z1);
                z2 = fma2(w3ap[2*c+2], v1.x, z2);
                z3 = fma2(w3ap[2*c+3], v1.y, z3);
            }
            unpack2(z0,l0,h0); unpack2(z1,l1,h1); unpack2(z2,l2,h2); unpack2(z3,l3,h3);
            g_z[p*32 + lane] = (l0+h0)+(l1+h1)+(l2+h2)+(l3+h3);
        }
    }
}

// ---------------------------------------------------------------------------
// Kernel B: persistent, warp-autonomous; each warp owns 4 consecutive points.
// Phases 0-2 per point; W4 epilogue batched over the 4 points (weights read
// once per 4 points, outputs stored as STG.128).
__global__ void __launch_bounds__(256, 3) kernelB(
    const float* __restrict__ xyz, const int* __restrict__ neigh32,
    const float* __restrict__ W1, const float* __restrict__ g1, const float* __restrict__ b1,
    const float* __restrict__ W3, const float* __restrict__ g3, const float* __restrict__ b3,
    const float* __restrict__ W4, const float* __restrict__ g4, const float* __restrict__ b4,
    float* __restrict__ out)
{
    __shared__ __align__(16) unsigned long long sW4o[64*32]; // [o][c_pair], scale folded
    __shared__ __align__(16) float sR[8][16*4];              // per-warp (dist,rx,ry,rz)x16
    __shared__ __align__(16) float sH1[8][16*32];            // per-warp h1[k][h]
    __shared__ __align__(16) float sE[8][4][64];             // per-warp operand, 4 points

    const int tid  = threadIdx.x;
    const int lane = tid & 31;
    const int wid  = tid >> 5;
    const float inv = rsqrtf(1.0f + 1e-5f);

    // W1 folded: u=[dist,r,P,Q], Q=P-r => W1@u = wd*dist + (Wr-WQ)@r + (WP+WQ)@P
    const float s1 = g1[lane]*inv, bb1 = b1[lane];
    const float s3 = g3[lane]*inv, bb3 = b3[lane];
    float wd   = W1[lane*10 + 0]*s1;
    float wrx  = (W1[lane*10 + 1] - W1[lane*10 + 7])*s1;
    float wry  = (W1[lane*10 + 2] - W1[lane*10 + 8])*s1;
    float wrz  = (W1[lane*10 + 3] - W1[lane*10 + 9])*s1;
    float wpx  = (W1[lane*10 + 4] + W1[lane*10 + 7])*s1;
    float wpy  = (W1[lane*10 + 5] + W1[lane*10 + 8])*s1;
    float wpz  = (W1[lane*10 + 6] + W1[lane*10 + 9])*s1;
    const unsigned long long w1a = pack2(wd,  wrx);   // * (dist, rx)
    const unsigned long long w1b = pack2(wry, wrz);   // * (ry, rz)

    // stage W3 coalesced into sH1, read rows (pitch 66)
    unsigned long long w3bp[16];
    {
        float* wt = (float*)sH1;
        for (int i = tid; i < 2048; i += 256) wt[(i>>6)*66 + (i&63)] = W3[i];
        __syncthreads();
        #pragma unroll
        for (int c = 0; c < 16; c++)
            w3bp[c] = pack2(wt[lane*66 + 32 + 2*c]*s3, wt[lane*66 + 33 + 2*c]*s3);
        __syncthreads();
    }
    // W4: sW4o[o*32 + cp] = (W4[o][2cp]*s4, W4[o][2cp+1]*s4)
    for (int i = tid; i < 2048; i += 256){
        int o = i >> 5, cp = i & 31;
        float s4 = g4[o]*inv;
        sW4o[i] = pack2(W4[o*64 + 2*cp]*s4, W4[o*64 + 2*cp + 1]*s4);
    }
    const float b4A = b4[lane], b4B = b4[lane + 32];

    const int is64 = g_is64;
    __syncthreads();

    const int NGRP = PT/32;
    #pragma unroll 1
    for (int grp = blockIdx.x; grp < NGRP; grp += gridDim.x){
        const int p0 = grp*32 + wid*4;            // this warp's 4 points (same batch)
        const int b  = p0 / NN;
        const int n0 = p0 - b*NN;
        const float* xb = xyz + (long)b*NN*3;
        const float* zb = g_z + (long)b*NN*32;

        #pragma unroll 1
        for (int j = 0; j < 4; j++){
            const int p = p0 + j;
            const int n = n0 + j;
            const float Px = xb[n*3+0], Py = xb[n*3+1], Pz = xb[n*3+2];

            // phase 0: lanes<16 compute their neighbor's geometry in parallel
            int myidx = 0;
            if (lane < 16){
                myidx = is64 ? neigh32[2*(p*16 + lane)] : neigh32[p*16 + lane];
                float Qx = xb[myidx*3+0], Qy = xb[myidx*3+1], Qz = xb[myidx*3+2];
                float rx = Px - Qx, ry = Py - Qy, rz = Pz - Qz;
                float dist = sqrtf(rx*rx + ry*ry + rz*rz);
                ((float4*)sR[wid])[lane] = make_float4(dist, rx, ry, rz);
            }

            // batched z gathers (MLP=16)
            float zk[16];
            #pragma unroll
            for (int k = 0; k < 16; k++){
                int id = __shfl_sync(0xffffffffu, myidx, k);
                zk[k] = zb[id*32 + lane];
            }
            __syncwarp();

            const unsigned long long basep =
                pack2(fmaf(wpx, Px, fmaf(wpy, Py, fmaf(wpz, Pz, bb1))), 0.0f);

            // phase 1: h1 for all 16 neighbors
            float* h1w = sH1[wid];
            const ulonglong2* rp = (const ulonglong2*)sR[wid];
            #pragma unroll
            for (int k = 0; k < 16; k++){
                ulonglong2 rv = rp[k];
                unsigned long long acc = fma2(w1a, rv.x, basep);
                acc = fma2(w1b, rv.y, acc);
                float lo, hi; unpack2(acc, lo, hi);
                h1w[k*32 + lane] = fmaxf(lo + hi, 0.0f);
            }
            __syncwarp();

            // phase 2: y_k = z_k + W3b @ h1_k ; max over k (b3 hoisted)
            float maxv = -3.4e38f;
            #pragma unroll
            for (int k = 0; k < 16; k++){
                const ulonglong2* hp2 = (const ulonglong2*)(h1w + k*32);
                unsigned long long c0 = pack2(zk[k], 0.0f), c1=0ull, c2=0ull, c3=0ull;
                #pragma unroll
                for (int c = 0; c < 8; c += 2){
                    ulonglong2 v0 = hp2[c], v1 = hp2[c+1];
                    c0 = fma2(w3bp[2*c+0], v0.x, c0);
                    c1 = fma2(w3bp[2*c+1], v0.y, c1);
                    c2 = fma2(w3bp[2*c+2], v1.x, c2);
                    c3 = fma2(w3bp[2*c+3], v1.y, c3);
                }
                float l0,h0,l1,h1v,l2,h2,l3,h3;
                unpack2(c0,l0,h0); unpack2(c1,l1,h1v); unpack2(c2,l2,h2); unpack2(c3,l3,h3);
                float y = (l0+h0)+(l1+h1v)+(l2+h2)+(l3+h3);
                maxv = fmaxf(maxv, y);
            }
            maxv = fmaxf(maxv + bb3, 0.0f);   // relu commutes with max

            // stage operand for batched epilogue
            sE[wid][j][lane]      = maxv;
            sE[wid][j][32 + lane] = g_f[(long)p*32 + lane];
            __syncwarp();   // also protects sR/sH1 reuse next j
        }

        // batched W4 epilogue: lane computes outputs (lane, lane+32) x 4 points
        {
            unsigned long long aA0=0ull,aA1=0ull,aA2=0ull,aA3=0ull;
            unsigned long long aB0=0ull,aB1=0ull,aB2=0ull,aB3=0ull;
            const ulonglong2* wA = (const ulonglong2*)(sW4o + lane*32);
            const ulonglong2* wB = (const ulonglong2*)(sW4o + (lane+32)*32);
            const ulonglong2* x0 = (const ulonglong2*)sE[wid][0];
            const ulonglong2* x1 = (const ulonglong2*)sE[wid][1];
            const ulonglong2* x2 = (const ulonglong2*)sE[wid][2];
            const ulonglong2* x3 = (const ulonglong2*)sE[wid][3];
            #pragma unroll
            for (int c2 = 0; c2 < 16; c2++){
                ulonglong2 wa = wA[c2], wb = wB[c2];
                ulonglong2 v0 = x0[c2], v1 = x1[c2], v2 = x2[c2], v3 = x3[c2];
                aA0 = fma2(wa.x, v0.x, aA0); aA0 = fma2(wa.y, v0.y, aA0);
                aA1 = fma2(wa.x, v1.x, aA1); aA1 = fma2(wa.y, v1.y, aA1);
                aA2 = fma2(wa.x, v2.x, aA2); aA2 = fma2(wa.y, v2.y, aA2);
                aA3 = fma2(wa.x, v3.x, aA3); aA3 = fma2(wa.y, v3.y, aA3);
                aB0 = fma2(wb.x, v0.x, aB0); aB0 = fma2(wb.y, v0.y, aB0);
                aB1 = fma2(wb.x, v1.x, aB1); aB1 = fma2(wb.y, v1.y, aB1);
                aB2 = fma2(wb.x, v2.x, aB2); aB2 = fma2(wb.y, v2.y, aB2);
                aB3 = fma2(wb.x, v3.x, aB3); aB3 = fma2(wb.y, v3.y, aB3);
            }
            float lo, hi;
            float4 yA, yB;
            unpack2(aA0, lo, hi); yA.x = fmaxf(lo + hi + b4A, 0.0f);
            unpack2(aA1, lo, hi); yA.y = fmaxf(lo + hi + b4A, 0.0f);
            unpack2(aA2, lo, hi); yA.z = fmaxf(lo + hi + b4A, 0.0f);
            unpack2(aA3, lo, hi); yA.w = fmaxf(lo + hi + b4A, 0.0f);
            unpack2(aB0, lo, hi); yB.x = fmaxf(lo + hi + b4B, 0.0f);
            unpack2(aB1, lo, hi); yB.y = fmaxf(lo + hi + b4B, 0.0f);
            unpack2(aB2, lo, hi); yB.z = fmaxf(lo + hi + b4B, 0.0f);
            unpack2(aB3, lo, hi); yB.w = fmaxf(lo + hi + b4B, 0.0f);
            *(float4*)(out + ((long)b*64 + lane)*NN + n0)      = yA;
            *(float4*)(out + ((long)b*64 + lane + 32)*NN + n0) = yB;
        }
        __syncwarp();
    }
}

// ---------------------------------------------------------------------------
extern "C" void kernel_launch(void* const* d_in, const int* in_sizes, int n_in,
                              void* d_out, int out_size)
{
    const float *feature=0, *xyzp=0, *W1=0, *W2=0, *W3=0, *W4=0;
    const void* neigh=0;
    const float* s32[6] = {0,0,0,0,0,0};   // g1,b1,g2,b2,g3,b3 (encounter order)
    const float* s64[2] = {0,0};           // g4,b4
    int n2048 = 0, c32 = 0, c64 = 0;
    for (int i = 0; i < n_in; i++){
        int sz = in_sizes[i];
        const float* p = (const float*)d_in[i];
        if      (sz == 10485760) feature = p;
        else if (sz == 491520)   xyzp = p;
        else if (sz == 2621440)  neigh = d_in[i];
        else if (sz == 320)      W1 = p;
        else if (sz == 2048)     { if (n2048++ == 0) W2 = p; else W3 = p; }
        else if (sz == 4096)     W4 = p;
        else if (sz == 32)       { if (c32 < 6) s32[c32++] = p; }
        else if (sz == 64)       { if (c64 < 2) s64[c64++] = p; }
    }

    kernelA<<<1184, 256>>>(feature, W2, s32[2], s32[3], W3, s32[4], (const int*)neigh);
    kernelB<<<444, 256>>>(xyzp, (const int*)neigh,
                          W1, s32[0], s32[1],
                          W3, s32[4], s32[5],
                          W4, s64[0], s64[1],
                          (float*)d_out);
}